// round 16
// baseline (speedup 1.0000x reference)
#include <cuda_runtime.h>
#include <cuda_bf16.h>
#include <cstdint>

// Problem constants
#define G   7
#define BSZ 8
#define MSZ 512
#define NSZ 512
#define KSZ 1024
// x zp = -66, y zp = 160.  out = xs*ys * sum_k (x+66)*(y-160)
// x+66 in [-62,193], y-160 in [-160,95]: both EXACT in bf16 -> no corrections.
// Magic int->bf16: bf16(v+66) = cvt(as_float(0x4B000000 + (v+322)) - 8388864.0f)
//   (v+322 >= 0 for v >= -322, so the float-bits trick is exact; all values
//    are integers << 2^24 so every fp op is exact.)

#define XELEMS ((size_t)G * BSZ * MSZ * KSZ)   // 29360128
#define YELEMS ((size_t)BSZ * KSZ * NSZ)       // 4194304

// ---- arch-specific feature gate (tcgen05 only legal on sm_103a pass) ----
#if defined(__CUDA_ARCH_FEAT_SM103_ALL) || \
    (defined(__CUDA_ARCH_SPECIFIC__) && (__CUDA_ARCH_SPECIFIC__ == 1030)) || \
    (defined(__CUDA_ARCH_FAMILY_SPECIFIC__) && (__CUDA_ARCH_FAMILY_SPECIFIC__ == 1030))
#define TC_OK 1
#endif

// ---------------- tcgen05 bf16 GEMM tiling ----------------
#define BMG 128
#define BNG 256
#define BKE 64              // K elems per stage
#define NSTG (KSZ / BKE)    // 16
// smem: A bf16 1x16KB (single buffer), B bf16 3x32KB ring -> 114.7KB, 2 CTAs/SM
#define SM_AB     0
#define SM_BB(b)  (16384 + (b) * 32768)
#define SM_TMEMP  114688
#define SM_MBAR0  114696
#define SM_MBAR1  114704
#define DSMEM_TC  114720

// Scratch (allocation-free: __device__ global)
__device__ __align__(16) uint16_t g_ytb[YELEMS];  // (y-160) transposed bf16 [b][n][k]

// ---------------------------------------------------------------------------
// helpers
// ---------------------------------------------------------------------------
__device__ __forceinline__ uint32_t smem_u32(const void* p) {
    uint32_t a;
    asm("{ .reg .u64 t; cvta.to.shared.u64 t, %1; cvt.u32.u64 %0, t; }" : "=r"(a) : "l"(p));
    return a;
}
__device__ __forceinline__ void cp16(uint32_t dst, const void* src) {
    asm volatile("cp.async.cg.shared.global [%0], [%1], 16;" :: "r"(dst), "l"(src));
}
// pack two f32 into bf16x2: lo -> low half, hi -> high half
__device__ __forceinline__ uint32_t bf2(float lo, float hi) {
    uint32_t r;
    asm("cvt.rn.bf16x2.f32 %0, %1, %2;" : "=r"(r) : "f"(hi), "f"(lo));
    return r;
}

// ---------------------------------------------------------------------------
// Kernel 1: transpose y [b][k][n] -> g_ytb [b][n][k] = bf16(y - 160)
// magic conversion: byte b in [0,255]: f = as_float(0x4B000000+b) - 8388768.0f
// ---------------------------------------------------------------------------
__global__ __launch_bounds__(256) void transpose_y_kernel(const void* __restrict__ yin) {
    __shared__ __align__(16) uint8_t s[32][136];
    int b  = blockIdx.z;
    int n0 = blockIdx.x * 128;
    int k0 = blockIdx.y * 32;
    int t  = threadIdx.x;

    int fmt = 1;
    {
        const int* yi = (const int*)yin;
        #pragma unroll
        for (int j = 0; j < 8; j++) { int v = yi[j]; fmt &= (v >= 0 && v < 256); }
    }

    #pragma unroll
    for (int i = 0; i < 4; i++) {
        int w  = t + i * 256;
        int k  = w >> 5;
        int nw = w & 31;
        size_t base = ((size_t)(b * KSZ + k0 + k)) * NSZ + n0 + nw * 4;
        uint32_t wv;
        if (fmt) {
            int4 v = *(const int4*)((const int*)yin + base);
            wv = (v.x & 0xff) | ((v.y & 0xff) << 8) | ((v.z & 0xff) << 16) | ((uint32_t)(v.w & 0xff) << 24);
        } else {
            wv = *(const uint32_t*)((const uint8_t*)yin + base);
        }
        *(uint32_t*)&s[k][nw * 4] = wv;
    }
    __syncthreads();
    #pragma unroll
    for (int i = 0; i < 4; i++) {
        int w  = t + i * 256;
        int n  = w >> 3;
        int kq = w & 7;
        float f0 = __int_as_float(0x4B000000 + (int)s[kq * 4 + 0][n]) - 8388768.0f;
        float f1 = __int_as_float(0x4B000000 + (int)s[kq * 4 + 1][n]) - 8388768.0f;
        float f2 = __int_as_float(0x4B000000 + (int)s[kq * 4 + 2][n]) - 8388768.0f;
        float f3 = __int_as_float(0x4B000000 + (int)s[kq * 4 + 3][n]) - 8388768.0f;
        uint2 o;
        o.x = bf2(f0, f1);
        o.y = bf2(f2, f3);
        *(uint2*)(g_ytb + ((size_t)(b * NSZ + n0 + n)) * KSZ + k0 + kq * 4) = o;
    }
}

// ---------------------------------------------------------------------------
// Kernel 2: fused tcgen05 bf16 GEMM. A int32->bf16 in registers (magic cvt,
// no I2F). Single A smem buffer + 3-stage B ring. Tile 128(M) x 256(N).
// ---------------------------------------------------------------------------
#ifdef TC_OK
__device__ __forceinline__ uint32_t sw128(uint32_t off) { return off ^ ((off >> 3) & 0x70); }
__device__ __forceinline__ uint32_t elect_one() {
    uint32_t p;
    asm volatile("{\n\t.reg .pred P;\n\telect.sync _|P, 0xFFFFFFFF;\n\tselp.b32 %0, 1, 0, P;\n\t}" : "=r"(p));
    return p;
}
__device__ __forceinline__ void mbar_init(uint32_t a, uint32_t cnt) {
    asm volatile("mbarrier.init.shared.b64 [%0], %1;" :: "r"(a), "r"(cnt) : "memory");
}
__device__ __forceinline__ void mbar_wait(uint32_t a, uint32_t parity) {
    asm volatile(
        "{\n\t.reg .pred P;\n\t"
        "W%=:\n\t"
        "mbarrier.try_wait.parity.acquire.cta.shared::cta.b64 P, [%0], %1, 0x989680;\n\t"
        "@P bra D%=;\n\t"
        "bra W%=;\n\t"
        "D%=:\n\t}"
        :: "r"(a), "r"(parity) : "memory");
}
__device__ __forceinline__ uint64_t smem_desc(uint32_t addr) {
    const uint64_t base = (uint64_t(2) << 61) | (uint64_t(1) << 46) | (uint64_t(64) << 32) | (uint64_t(1) << 16);
    return base | ((uint64_t)(addr >> 4) & 0x3FFF);
}
#define IDESC_MAIN ((1u << 4) | (1u << 7) | (1u << 10) | ((BNG / 8) << 17) | ((BMG / 16) << 24))
__device__ __forceinline__ void mma_bf16(uint32_t d, uint64_t ad, uint64_t bd, uint32_t en) {
    asm volatile(
        "{\n\t.reg .pred p;\n\tsetp.ne.u32 p, %5, 0;\n\t"
        "tcgen05.mma.cta_group::1.kind::f16 [%0], %1, %2, %3, {%4, %4, %4, %4}, p;\n\t}"
        :: "r"(d), "l"(ad), "l"(bd), "r"((uint32_t)IDESC_MAIN), "r"(0u), "r"(en) : "memory");
}
#endif

__global__ __launch_bounds__(256, 2) void gemm_fused(const void* __restrict__ xin,
                                                     const float* __restrict__ xs,
                                                     const float* __restrict__ ys,
                                                     float* __restrict__ out) {
#ifdef TC_OK
    extern __shared__ __align__(1024) uint8_t smem[];
    const uint32_t sb = smem_u32(smem);
    const int t = threadIdx.x, wid = t >> 5, lane = t & 31;
    const int z = blockIdx.z, b = z & 7;
    const int m0 = blockIdx.y * BMG;
    const int n0 = blockIdx.x * BNG;

    // inline x-format probe (uniform across block)
    int fmt = 1;
    {
        const int* xi = (const int*)xin;
        #pragma unroll
        for (int j = 0; j < 8; j++) { int v = xi[j]; fmt &= (v >= -128 && v < 128); }
    }

    // A ownership (int32 path): warp w rows 16w..16w+15
    const int rsel  = lane >> 4;        // 0/1
    const int off16 = lane & 15;        // 16B chunk within 256B row-segment
    // legacy ownership for raw-s8 fallback
    const int arow = t >> 1, ahalf = t & 1;
    const size_t zstride = (size_t)z * MSZ + m0;
    const uint16_t* ybp = g_ytb + (size_t)b * NSZ * KSZ + (size_t)n0 * KSZ;

    const int   MB = 0x4B000000 + 322;   // int magic (folds +66 via +322/-256)
    const float FS = -8388864.0f;        // -(8388608 + 256)

    int4 r[8];   // A register staging

    auto ldgA = [&](int s) {
        if (fmt) {
            #pragma unroll
            for (int i = 0; i < 8; i++) {
                int row = wid * 16 + 2 * i + rsel;
                const int4* p = (const int4*)xin +
                    ((zstride + row) * KSZ + s * BKE) / 4 + off16;
                r[i] = *p;
            }
        } else {
            const int4* p = (const int4*)((const uint8_t*)xin +
                (zstride + arow) * KSZ + s * BKE + ahalf * 32);
            r[0] = p[0]; r[1] = p[1];
        }
    };
    auto stsA = [&]() {
        uint8_t* abp = smem + SM_AB;
        if (fmt) {
            #pragma unroll
            for (int i = 0; i < 8; i++) {
                int row = wid * 16 + 2 * i + rsel;
                float fx = __int_as_float(r[i].x + MB) + FS;
                float fy = __int_as_float(r[i].y + MB) + FS;
                float fz = __int_as_float(r[i].z + MB) + FS;
                float fw = __int_as_float(r[i].w + MB) + FS;
                uint2 o;
                o.x = bf2(fx, fy);
                o.y = bf2(fz, fw);
                *(uint2*)(abp + sw128(row * 128 + off16 * 8)) = o;
            }
        } else {
            #pragma unroll
            for (int j = 0; j < 4; j++) {
                uint32_t w0 = (j < 2) ? ((j & 1) ? (uint32_t)r[0].z : (uint32_t)r[0].x)
                                      : ((j & 1) ? (uint32_t)r[1].z : (uint32_t)r[1].x);
                uint32_t w1 = (j < 2) ? ((j & 1) ? (uint32_t)r[0].w : (uint32_t)r[0].y)
                                      : ((j & 1) ? (uint32_t)r[1].w : (uint32_t)r[1].y);
                float f0 = __int_as_float(((int)(int8_t)(w0) + MB)) + FS;
                float f1 = __int_as_float(((int)(int8_t)(w0 >> 8) + MB)) + FS;
                float f2 = __int_as_float(((int)(int8_t)(w0 >> 16) + MB)) + FS;
                float f3 = __int_as_float(((int)(int8_t)(w0 >> 24) + MB)) + FS;
                float f4 = __int_as_float(((int)(int8_t)(w1) + MB)) + FS;
                float f5 = __int_as_float(((int)(int8_t)(w1 >> 8) + MB)) + FS;
                float f6 = __int_as_float(((int)(int8_t)(w1 >> 16) + MB)) + FS;
                float f7 = __int_as_float(((int)(int8_t)(w1 >> 24) + MB)) + FS;
                uint4 o;
                o.x = bf2(f0, f1); o.y = bf2(f2, f3);
                o.z = bf2(f4, f5); o.w = bf2(f6, f7);
                *(uint4*)(abp + sw128(arow * 128 + (ahalf * 4 + j) * 16)) = o;
            }
        }
    };
    auto loadB = [&](int s, int slot) {
        uint32_t bbb = sb + SM_BB(slot);
        #pragma unroll
        for (int i = 0; i < 8; i++) {          // 256 rows x 128B = 2048 chunks / 256 thr
            int id = t + i * 256;
            int row = id >> 3, c = (id & 7) << 4;
            cp16(bbb + sw128(row * 128 + c),
                 (const uint8_t*)(ybp + (size_t)row * KSZ) + s * 128 + c);
        }
        asm volatile("cp.async.commit_group;" ::: "memory");
    };

    // prologue: A regs + B stages 0,1 in flight BEFORE (possibly blocking) alloc
    ldgA(0);
    loadB(0, 0);
    loadB(1, 1);

    if (wid == 0) {
        asm volatile("tcgen05.alloc.cta_group::1.sync.aligned.shared::cta.b32 [%0], %1;"
                     :: "r"(sb + SM_TMEMP), "r"(256u) : "memory");
        asm volatile("tcgen05.relinquish_alloc_permit.cta_group::1.sync.aligned;" ::: "memory");
    }
    if (t == 0) { mbar_init(sb + SM_MBAR0, 1); mbar_init(sb + SM_MBAR1, 1); }
    __syncthreads();
    uint32_t tmem;
    asm volatile("ld.shared.b32 %0, [%1];" : "=r"(tmem) : "r"(sb + SM_TMEMP));

    int ph0 = 0, ph1 = 0;
    const uint64_t ad = smem_desc(sb + SM_AB);

    for (int s = 0; s < NSTG; s++) {
        // wait MMA(s-1): frees the single A buffer and B slot (s+2)%3
        if (s >= 1) {
            if (((s - 1) & 1) == 0) { mbar_wait(sb + SM_MBAR0, ph0); ph0 ^= 1; }
            else                    { mbar_wait(sb + SM_MBAR1, ph1); ph1 ^= 1; }
        }
        if (s + 2 < NSTG) {
            loadB(s + 2, (s + 2) % 3);
            asm volatile("cp.async.wait_group 2;" ::: "memory");   // B(s) arrived
        } else if (s + 1 < NSTG) {
            asm volatile("cp.async.wait_group 1;" ::: "memory");
        } else {
            asm volatile("cp.async.wait_group 0;" ::: "memory");
        }
        stsA();                          // regs(s) -> swizzled bf16 A
        if (s + 1 < NSTG) ldgA(s + 1);   // prefetch next A into regs
        __syncthreads();                 // A STS + B visible to all
        asm volatile("fence.proxy.async.shared::cta;" ::: "memory");

        if (wid == 0) {
            asm volatile("tcgen05.fence::after_thread_sync;" ::: "memory");
            if (elect_one()) {
                uint64_t bd = smem_desc(sb + SM_BB(s % 3));
                #pragma unroll
                for (int k = 0; k < 4; k++) {   // 4 x K=16 per stage
                    mma_bf16(tmem, ad + k * 2, bd + k * 2, (uint32_t)(s * 4 + k));
                }
                asm volatile("tcgen05.commit.cta_group::1.mbarrier::arrive::one.shared::cluster.b64 [%0];"
                             :: "r"(sb + ((s & 1) ? SM_MBAR1 : SM_MBAR0)) : "memory");
            }
        }
    }

    // MMA(15) committed to mbar1; covers all prior mma
    mbar_wait(sb + SM_MBAR1, ph1);
    asm volatile("tcgen05.fence::after_thread_sync;" ::: "memory");
    __syncthreads();

    // epilogue over all 8 warps: warp w reads TMEM subpartition (w&3),
    // column chunks (w>>2)*4 .. +3
    const float sc = xs[0] * ys[0];
    float* tile = (float*)(smem + wid * 4352);   // 8 x 32x33 f32 tiles (34.8KB)
    const int part = wid & 3;
    const int cbase = (wid >> 2) * 4;

    #pragma unroll 1
    for (int ci = 0; ci < 4; ci++) {
        const int chunk = cbase + ci;
        uint32_t d[32];
        asm volatile(
            "tcgen05.ld.sync.aligned.32x32b.x32.b32 "
            "{%0,%1,%2,%3,%4,%5,%6,%7,%8,%9,%10,%11,%12,%13,%14,%15,"
            "%16,%17,%18,%19,%20,%21,%22,%23,%24,%25,%26,%27,%28,%29,%30,%31}, [%32];"
            : "=r"(d[0]), "=r"(d[1]), "=r"(d[2]), "=r"(d[3]), "=r"(d[4]), "=r"(d[5]), "=r"(d[6]), "=r"(d[7]),
              "=r"(d[8]), "=r"(d[9]), "=r"(d[10]), "=r"(d[11]), "=r"(d[12]), "=r"(d[13]), "=r"(d[14]), "=r"(d[15]),
              "=r"(d[16]), "=r"(d[17]), "=r"(d[18]), "=r"(d[19]), "=r"(d[20]), "=r"(d[21]), "=r"(d[22]), "=r"(d[23]),
              "=r"(d[24]), "=r"(d[25]), "=r"(d[26]), "=r"(d[27]), "=r"(d[28]), "=r"(d[29]), "=r"(d[30]), "=r"(d[31])
            : "r"(tmem + chunk * 32));
        asm volatile("tcgen05.wait::ld.sync.aligned;" ::: "memory");

        #pragma unroll
        for (int c = 0; c < 32; c++) {
            tile[lane * 33 + c] = sc * __uint_as_float(d[c]);
        }
        __syncwarp();
        #pragma unroll
        for (int rr = 0; rr < 32; rr++) {
            out[((size_t)z * MSZ + m0 + part * 32 + rr) * NSZ + n0 + chunk * 32 + lane] = tile[rr * 33 + lane];
        }
        __syncwarp();
    }

    __syncthreads();
    if (wid == 0) {
        asm volatile("tcgen05.dealloc.cta_group::1.sync.aligned.b32 %0, %1;" :: "r"(tmem), "r"(256u));
    }
#endif
}

// ---------------------------------------------------------------------------
extern "C" void kernel_launch(void* const* d_in, const int* in_sizes, int n_in,
                              void* d_out, int out_size) {
    const void* x = nullptr;
    const void* y = nullptr;
    const float* xs = nullptr;
    const float* ys = nullptr;

    for (int i = 0; i < n_in; i++) {
        long sz = in_sizes[i];
        if (sz == (long)XELEMS) x = d_in[i];
        else if (sz == (long)YELEMS) y = d_in[i];
        else if (xs == nullptr) xs = (const float*)d_in[i];
        else if (ys == nullptr) ys = (const float*)d_in[i];
    }
    float* out = (float*)d_out;

    cudaFuncSetAttribute(gemm_fused, cudaFuncAttributeMaxDynamicSharedMemorySize, DSMEM_TC);

    transpose_y_kernel<<<dim3(NSZ / 128, KSZ / 32, BSZ), 256>>>(y);
    gemm_fused<<<dim3(NSZ / BNG, MSZ / BMG, G * BSZ), 256, DSMEM_TC>>>(x, xs, ys, out);
}

// round 17
// speedup vs baseline: 1.3035x; 1.3035x over previous
#include <cuda_runtime.h>
#include <cuda_bf16.h>
#include <cstdint>

// Problem constants
#define G   7
#define BSZ 8
#define MSZ 512
#define NSZ 512
#define KSZ 1024
// x zp = -66, y zp = 160.  out = xs*ys * sum_k (x+66)*(y-160)
// x+66 in [-62,193], y-160 in [-160,95]: both EXACT in bf16 -> no corrections.
// Magic int->bf16 (no I2F): bf16(v+66) = cvt(as_float(0x4B000000+(v+322)) - 8388864.0f)

#define XELEMS ((size_t)G * BSZ * MSZ * KSZ)   // 29360128
#define YELEMS ((size_t)BSZ * KSZ * NSZ)       // 4194304

// ---- arch-specific feature gate (tcgen05 only legal on sm_103a pass) ----
#if defined(__CUDA_ARCH_FEAT_SM103_ALL) || \
    (defined(__CUDA_ARCH_SPECIFIC__) && (__CUDA_ARCH_SPECIFIC__ == 1030)) || \
    (defined(__CUDA_ARCH_FAMILY_SPECIFIC__) && (__CUDA_ARCH_FAMILY_SPECIFIC__ == 1030))
#define TC_OK 1
#endif

// ---------------- tcgen05 bf16 GEMM tiling (R12 layout: 96KB, 2 CTAs/SM) ---
#define BMG 128
#define BNG 256
#define BKE 64              // K elems per stage
#define NSTG (KSZ / BKE)    // 16
#define SM_AB(b)  ((b) * 16384)
#define SM_BB(b)  (32768 + (b) * 32768)
#define SM_TMEMP  98304
#define SM_MBAR0  98312
#define SM_MBAR1  98320
#define DSMEM_TC  98336

// Scratch (allocation-free: __device__ global)
__device__ __align__(16) uint16_t g_ytb[YELEMS];  // (y-160) transposed bf16 [b][n][k]

// ---------------------------------------------------------------------------
// helpers
// ---------------------------------------------------------------------------
__device__ __forceinline__ uint32_t smem_u32(const void* p) {
    uint32_t a;
    asm("{ .reg .u64 t; cvta.to.shared.u64 t, %1; cvt.u32.u64 %0, t; }" : "=r"(a) : "l"(p));
    return a;
}
__device__ __forceinline__ void cp16(uint32_t dst, const void* src) {
    asm volatile("cp.async.cg.shared.global [%0], [%1], 16;" :: "r"(dst), "l"(src));
}
// pack two f32 into bf16x2: lo -> low half, hi -> high half
__device__ __forceinline__ uint32_t bf2(float lo, float hi) {
    uint32_t r;
    asm("cvt.rn.bf16x2.f32 %0, %1, %2;" : "=r"(r) : "f"(hi), "f"(lo));
    return r;
}

// ---------------------------------------------------------------------------
// Kernel 1: transpose y [b][k][n] -> g_ytb [b][n][k] = bf16(y - 160)
// magic conversion: byte v in [0,255]: f = as_float(0x4B000000+v) - 8388768.0f
// ---------------------------------------------------------------------------
__global__ __launch_bounds__(256) void transpose_y_kernel(const void* __restrict__ yin) {
    __shared__ __align__(16) uint8_t s[32][136];
    int b  = blockIdx.z;
    int n0 = blockIdx.x * 128;
    int k0 = blockIdx.y * 32;
    int t  = threadIdx.x;

    int fmt = 1;
    {
        const int* yi = (const int*)yin;
        #pragma unroll
        for (int j = 0; j < 8; j++) { int v = yi[j]; fmt &= (v >= 0 && v < 256); }
    }

    #pragma unroll
    for (int i = 0; i < 4; i++) {
        int w  = t + i * 256;
        int k  = w >> 5;
        int nw = w & 31;
        size_t base = ((size_t)(b * KSZ + k0 + k)) * NSZ + n0 + nw * 4;
        uint32_t wv;
        if (fmt) {
            int4 v = *(const int4*)((const int*)yin + base);
            wv = (v.x & 0xff) | ((v.y & 0xff) << 8) | ((v.z & 0xff) << 16) | ((uint32_t)(v.w & 0xff) << 24);
        } else {
            wv = *(const uint32_t*)((const uint8_t*)yin + base);
        }
        *(uint32_t*)&s[k][nw * 4] = wv;
    }
    __syncthreads();
    #pragma unroll
    for (int i = 0; i < 4; i++) {
        int w  = t + i * 256;
        int n  = w >> 3;
        int kq = w & 7;
        float f0 = __int_as_float(0x4B000000 + (int)s[kq * 4 + 0][n]) - 8388768.0f;
        float f1 = __int_as_float(0x4B000000 + (int)s[kq * 4 + 1][n]) - 8388768.0f;
        float f2 = __int_as_float(0x4B000000 + (int)s[kq * 4 + 2][n]) - 8388768.0f;
        float f3 = __int_as_float(0x4B000000 + (int)s[kq * 4 + 3][n]) - 8388768.0f;
        uint2 o;
        o.x = bf2(f0, f1);
        o.y = bf2(f2, f3);
        *(uint2*)(g_ytb + ((size_t)(b * NSZ + n0 + n)) * KSZ + k0 + kq * 4) = o;
    }
}

// ---------------------------------------------------------------------------
// Kernel 2: fused tcgen05 bf16 GEMM (R12 double-buffered pipeline).
// A int32->bf16 in registers via magic cvt (no I2F). Tile 128(M) x 256(N).
// ---------------------------------------------------------------------------
#ifdef TC_OK
__device__ __forceinline__ uint32_t sw128(uint32_t off) { return off ^ ((off >> 3) & 0x70); }
__device__ __forceinline__ uint32_t elect_one() {
    uint32_t p;
    asm volatile("{\n\t.reg .pred P;\n\telect.sync _|P, 0xFFFFFFFF;\n\tselp.b32 %0, 1, 0, P;\n\t}" : "=r"(p));
    return p;
}
__device__ __forceinline__ void mbar_init(uint32_t a, uint32_t cnt) {
    asm volatile("mbarrier.init.shared.b64 [%0], %1;" :: "r"(a), "r"(cnt) : "memory");
}
__device__ __forceinline__ void mbar_wait(uint32_t a, uint32_t parity) {
    asm volatile(
        "{\n\t.reg .pred P;\n\t"
        "W%=:\n\t"
        "mbarrier.try_wait.parity.acquire.cta.shared::cta.b64 P, [%0], %1, 0x989680;\n\t"
        "@P bra D%=;\n\t"
        "bra W%=;\n\t"
        "D%=:\n\t}"
        :: "r"(a), "r"(parity) : "memory");
}
__device__ __forceinline__ uint64_t smem_desc(uint32_t addr) {
    const uint64_t base = (uint64_t(2) << 61) | (uint64_t(1) << 46) | (uint64_t(64) << 32) | (uint64_t(1) << 16);
    return base | ((uint64_t)(addr >> 4) & 0x3FFF);
}
#define IDESC_MAIN ((1u << 4) | (1u << 7) | (1u << 10) | ((BNG / 8) << 17) | ((BMG / 16) << 24))
__device__ __forceinline__ void mma_bf16(uint32_t d, uint64_t ad, uint64_t bd, uint32_t en) {
    asm volatile(
        "{\n\t.reg .pred p;\n\tsetp.ne.u32 p, %5, 0;\n\t"
        "tcgen05.mma.cta_group::1.kind::f16 [%0], %1, %2, %3, {%4, %4, %4, %4}, p;\n\t}"
        :: "r"(d), "l"(ad), "l"(bd), "r"((uint32_t)IDESC_MAIN), "r"(0u), "r"(en) : "memory");
}
#endif

__global__ __launch_bounds__(256, 2) void gemm_fused(const void* __restrict__ xin,
                                                     const float* __restrict__ xs,
                                                     const float* __restrict__ ys,
                                                     float* __restrict__ out) {
#ifdef TC_OK
    extern __shared__ __align__(1024) uint8_t smem[];
    const uint32_t sb = smem_u32(smem);
    const int t = threadIdx.x, wid = t >> 5, lane = t & 31;
    const int z = blockIdx.z, b = z & 7;
    const int m0 = blockIdx.y * BMG;
    const int n0 = blockIdx.x * BNG;

    // inline x-format probe (uniform across block)
    int fmt = 1;
    {
        const int* xi = (const int*)xin;
        #pragma unroll
        for (int j = 0; j < 8; j++) { int v = xi[j]; fmt &= (v >= -128 && v < 128); }
    }

    // A ownership (int32 path): warp w rows 16w..16w+15
    const int rsel  = lane >> 4;        // 0/1
    const int off16 = lane & 15;        // 16B chunk within 256B row-segment
    // legacy ownership for raw-s8 fallback
    const int arow = t >> 1, ahalf = t & 1;
    const size_t zstride = (size_t)z * MSZ + m0;
    const uint16_t* ybp = g_ytb + (size_t)b * NSZ * KSZ + (size_t)n0 * KSZ;

    const int   MB = 0x4B000000 + 322;   // int magic (folds +66 via +322/-256)
    const float FS = -8388864.0f;        // -(8388608 + 256)

    int4 r[8];   // A register staging

    auto ldgA = [&](int s) {
        if (fmt) {
            #pragma unroll
            for (int i = 0; i < 8; i++) {
                int row = wid * 16 + 2 * i + rsel;
                const int4* p = (const int4*)xin +
                    ((zstride + row) * KSZ + s * BKE) / 4 + off16;
                r[i] = *p;
            }
        } else {
            const int4* p = (const int4*)((const uint8_t*)xin +
                (zstride + arow) * KSZ + s * BKE + ahalf * 32);
            r[0] = p[0]; r[1] = p[1];
        }
    };
    auto stsA = [&](int buf) {
        uint8_t* abp = smem + SM_AB(buf);
        if (fmt) {
            #pragma unroll
            for (int i = 0; i < 8; i++) {
                int row = wid * 16 + 2 * i + rsel;
                float fx = __int_as_float(r[i].x + MB) + FS;
                float fy = __int_as_float(r[i].y + MB) + FS;
                float fz = __int_as_float(r[i].z + MB) + FS;
                float fw = __int_as_float(r[i].w + MB) + FS;
                uint2 o;
                o.x = bf2(fx, fy);
                o.y = bf2(fz, fw);
                *(uint2*)(abp + sw128(row * 128 + off16 * 8)) = o;
            }
        } else {
            #pragma unroll
            for (int j = 0; j < 4; j++) {
                uint32_t w0 = (j < 2) ? ((j & 1) ? (uint32_t)r[0].z : (uint32_t)r[0].x)
                                      : ((j & 1) ? (uint32_t)r[1].z : (uint32_t)r[1].x);
                uint32_t w1 = (j < 2) ? ((j & 1) ? (uint32_t)r[0].w : (uint32_t)r[0].y)
                                      : ((j & 1) ? (uint32_t)r[1].w : (uint32_t)r[1].y);
                float f0 = __int_as_float(((int)(int8_t)(w0) + MB)) + FS;
                float f1 = __int_as_float(((int)(int8_t)(w0 >> 8) + MB)) + FS;
                float f2 = __int_as_float(((int)(int8_t)(w0 >> 16) + MB)) + FS;
                float f3 = __int_as_float(((int)(int8_t)(w0 >> 24) + MB)) + FS;
                float f4 = __int_as_float(((int)(int8_t)(w1) + MB)) + FS;
                float f5 = __int_as_float(((int)(int8_t)(w1 >> 8) + MB)) + FS;
                float f6 = __int_as_float(((int)(int8_t)(w1 >> 16) + MB)) + FS;
                float f7 = __int_as_float(((int)(int8_t)(w1 >> 24) + MB)) + FS;
                uint4 o;
                o.x = bf2(f0, f1); o.y = bf2(f2, f3);
                o.z = bf2(f4, f5); o.w = bf2(f6, f7);
                *(uint4*)(abp + sw128(arow * 128 + (ahalf * 4 + j) * 16)) = o;
            }
        }
    };
    auto loadB = [&](int s, int buf) {
        uint32_t bbb = sb + SM_BB(buf);
        #pragma unroll
        for (int i = 0; i < 8; i++) {          // 256 rows x 128B = 2048 chunks / 256 thr
            int id = t + i * 256;
            int row = id >> 3, c = (id & 7) << 4;
            cp16(bbb + sw128(row * 128 + c),
                 (const uint8_t*)(ybp + (size_t)row * KSZ) + s * 128 + c);
        }
        asm volatile("cp.async.commit_group;" ::: "memory");
    };

    // prologue: A regs + B stage 0 in flight BEFORE (possibly blocking) alloc
    ldgA(0);
    loadB(0, 0);

    if (wid == 0) {
        asm volatile("tcgen05.alloc.cta_group::1.sync.aligned.shared::cta.b32 [%0], %1;"
                     :: "r"(sb + SM_TMEMP), "r"(256u) : "memory");
        asm volatile("tcgen05.relinquish_alloc_permit.cta_group::1.sync.aligned;" ::: "memory");
    }
    if (t == 0) { mbar_init(sb + SM_MBAR0, 1); mbar_init(sb + SM_MBAR1, 1); }
    __syncthreads();
    uint32_t tmem;
    asm volatile("ld.shared.b32 %0, [%1];" : "=r"(tmem) : "r"(sb + SM_TMEMP));

    int ph0 = 0, ph1 = 0;

    for (int s = 0; s < NSTG; s++) {
        const int buf = s & 1;
        if (s + 1 < NSTG) {
            const int nb = buf ^ 1;
            if (s + 1 >= 2) {    // nb freed when MMA(s-1) completes
                if (nb == 0) { mbar_wait(sb + SM_MBAR0, ph0); ph0 ^= 1; }
                else         { mbar_wait(sb + SM_MBAR1, ph1); ph1 ^= 1; }
            }
            loadB(s + 1, nb);
            asm volatile("cp.async.wait_group 1;" ::: "memory");   // B(s) arrived
        } else {
            asm volatile("cp.async.wait_group 0;" ::: "memory");
        }
        stsA(buf);                       // regs(s) -> swizzled bf16 A(buf)
        if (s + 1 < NSTG) ldgA(s + 1);   // prefetch next A into regs
        __syncthreads();                 // A STS + B visible to all
        asm volatile("fence.proxy.async.shared::cta;" ::: "memory");

        if (wid == 0) {
            asm volatile("tcgen05.fence::after_thread_sync;" ::: "memory");
            if (elect_one()) {
                uint64_t ad = smem_desc(sb + SM_AB(buf));
                uint64_t bd = smem_desc(sb + SM_BB(buf));
                #pragma unroll
                for (int k = 0; k < 4; k++) {   // 4 x K=16 per stage
                    mma_bf16(tmem, ad + k * 2, bd + k * 2, (uint32_t)(s * 4 + k));
                }
                asm volatile("tcgen05.commit.cta_group::1.mbarrier::arrive::one.shared::cluster.b64 [%0];"
                             :: "r"(sb + (buf ? SM_MBAR1 : SM_MBAR0)) : "memory");
            }
        }
    }

    // stage 15 committed to mbar1; covers all prior mma
    mbar_wait(sb + SM_MBAR1, ph1);
    asm volatile("tcgen05.fence::after_thread_sync;" ::: "memory");
    __syncthreads();

    // epilogue over all 8 warps: warp w reads TMEM subpartition (w&3),
    // column chunks (w>>2)*4 .. +3
    const float sc = xs[0] * ys[0];
    float* tile = (float*)(smem + wid * 4352);   // 8 x 32x33 f32 tiles (34.8KB)
    const int part = wid & 3;
    const int cbase = (wid >> 2) * 4;

    #pragma unroll 1
    for (int ci = 0; ci < 4; ci++) {
        const int chunk = cbase + ci;
        uint32_t d[32];
        asm volatile(
            "tcgen05.ld.sync.aligned.32x32b.x32.b32 "
            "{%0,%1,%2,%3,%4,%5,%6,%7,%8,%9,%10,%11,%12,%13,%14,%15,"
            "%16,%17,%18,%19,%20,%21,%22,%23,%24,%25,%26,%27,%28,%29,%30,%31}, [%32];"
            : "=r"(d[0]), "=r"(d[1]), "=r"(d[2]), "=r"(d[3]), "=r"(d[4]), "=r"(d[5]), "=r"(d[6]), "=r"(d[7]),
              "=r"(d[8]), "=r"(d[9]), "=r"(d[10]), "=r"(d[11]), "=r"(d[12]), "=r"(d[13]), "=r"(d[14]), "=r"(d[15]),
              "=r"(d[16]), "=r"(d[17]), "=r"(d[18]), "=r"(d[19]), "=r"(d[20]), "=r"(d[21]), "=r"(d[22]), "=r"(d[23]),
              "=r"(d[24]), "=r"(d[25]), "=r"(d[26]), "=r"(d[27]), "=r"(d[28]), "=r"(d[29]), "=r"(d[30]), "=r"(d[31])
            : "r"(tmem + chunk * 32));
        asm volatile("tcgen05.wait::ld.sync.aligned;" ::: "memory");

        #pragma unroll
        for (int c = 0; c < 32; c++) {
            tile[lane * 33 + c] = sc * __uint_as_float(d[c]);
        }
        __syncwarp();
        #pragma unroll
        for (int rr = 0; rr < 32; rr++) {
            out[((size_t)z * MSZ + m0 + part * 32 + rr) * NSZ + n0 + chunk * 32 + lane] = tile[rr * 33 + lane];
        }
        __syncwarp();
    }

    __syncthreads();
    if (wid == 0) {
        asm volatile("tcgen05.dealloc.cta_group::1.sync.aligned.b32 %0, %1;" :: "r"(tmem), "r"(256u));
    }
#endif
}

// ---------------------------------------------------------------------------
extern "C" void kernel_launch(void* const* d_in, const int* in_sizes, int n_in,
                              void* d_out, int out_size) {
    const void* x = nullptr;
    const void* y = nullptr;
    const float* xs = nullptr;
    const float* ys = nullptr;

    for (int i = 0; i < n_in; i++) {
        long sz = in_sizes[i];
        if (sz == (long)XELEMS) x = d_in[i];
        else if (sz == (long)YELEMS) y = d_in[i];
        else if (xs == nullptr) xs = (const float*)d_in[i];
        else if (ys == nullptr) ys = (const float*)d_in[i];
    }
    float* out = (float*)d_out;

    cudaFuncSetAttribute(gemm_fused, cudaFuncAttributeMaxDynamicSharedMemorySize, DSMEM_TC);

    transpose_y_kernel<<<dim3(NSZ / 128, KSZ / 32, BSZ), 256>>>(y);
    gemm_fused<<<dim3(NSZ / BNG, MSZ / BMG, G * BSZ), 256, DSMEM_TC>>>(x, xs, ys, out);
}